// round 13
// baseline (speedup 1.0000x reference)
#include <cuda_runtime.h>

// Problem shapes (compile-time constants)
#define BATCH 8
#define NC    28
#define HH    256
#define WCC   310
#define WPP   256

static constexpr int HWC = HH * WCC;                 // 79360 (even)
static constexpr int HWP = HH * WPP;                 // 65536
static constexpr int NPIX_C = BATCH * HWC;           // 634880
static constexpr int NPIX_P = BATCH * HWP;           // 524288
static constexpr int XC_ELEMS = BATCH * NC * HWC;    // 17,776,640

// Work-unit schedule (one unit = 256 pixels = one R12 block):
//   16 groups x (155 xc + 128 xp) = 4528 units; each group covers half a
//   batch image in both domains so xp's shifted z reads hit L2.
static constexpr int XC_BLK_PER_GRP = 155;
static constexpr int GRP_BLKS = 283;
static constexpr int N_UNITS = 16 * GRP_BLKS;        // 4528

// Persistent grid: exactly 3 CTAs/SM x 148 SMs = 444 resident CTAs.
// Each CTA grid-strides over units in original order; the 444-wide resident
// window spans ~1.6 groups, preserving the L2 z-reuse locality, while the
// ragged 10.2-wave tail (~88/444 CTAs in the last wave) collapses to a
// 1-unit imbalance.
static constexpr int PERSIST_BLOCKS = 444;

__global__ void __launch_bounds__(128, 3)
dp_fused_kernel(const float* __restrict__ z,
                const float* __restrict__ yc,
                const float* __restrict__ phi_c,
                const float* __restrict__ yp,
                const float* __restrict__ phi_p,
                const float* __restrict__ xc_k_1,
                const float* __restrict__ xp_k_1,
                const float* __restrict__ mu,
                const float* __restrict__ mu_c,
                const float* __restrict__ mu_p,
                float* __restrict__ out)
{
    const float mu_  = mu[0];
    const float muc  = mu_c[0];
    const float mup  = mu_p[0];
    const float invc = 1.f / (mu_ + muc);
    const float invp = 1.f / (mu_ + mup);

    for (int u = blockIdx.x; u < N_UNITS; u += PERSIST_BLOCKS) {
        const int g = u / GRP_BLKS;
        const int j = u - g * GRP_BLKS;

        if (j < XC_BLK_PER_GRP) {
            // ---------------- xc update (coded domain, W=310) ----------------
            const int pix = ((g * XC_BLK_PER_GRP + j) * 128 + threadIdx.x) * 2;
            const float wA = muc * invc;
            const float wz = mu_ * invc;
            const int b    = pix / HWC;
            const int rem  = pix - b * HWC;          // even
            const int base = b * (NC * HWC) + rem;   // 8B aligned

            const float2 y2 = *(const float2*)(yc + pix);   // hoisted

            float2 mr[NC], pr[NC];
            float2 s  = make_float2(0.f, 0.f);
            float2 am = make_float2(0.f, 0.f);
            #pragma unroll
            for (int c = 0; c < NC; ++c) {
                const int o = base + c * HWC;
                const float2 zv = *(const float2*)(z      + o);
                const float2 pv = *(const float2*)(phi_c  + o);
                const float2 xv = *(const float2*)(xp_k_1 + o);
                float2 m;
                m.x = fmaf(wz, xv.x, wA * zv.x);
                m.y = fmaf(wz, xv.y, wA * zv.y);
                mr[c] = m; pr[c] = pv;
                s.x  = fmaf(pv.x, pv.x, s.x);
                s.y  = fmaf(pv.y, pv.y, s.y);
                am.x = fmaf(m.x, pv.x, am.x);
                am.y = fmaf(m.y, pv.y, am.y);
            }
            if (s.x == 0.f) s.x = 1.f;
            if (s.y == 0.f) s.y = 1.f;
            float2 t;
            t.x = __fdividef(y2.x - am.x, mu_ + muc + s.x);
            t.y = __fdividef(y2.y - am.y, mu_ + muc + s.y);

            #pragma unroll
            for (int c = 0; c < NC; ++c) {
                float2 o2;
                o2.x = fmaf(t.x, pr[c].x, mr[c].x);
                o2.y = fmaf(t.y, pr[c].y, mr[c].y);
                *(float2*)(out + base + c * HWC) = o2;
            }
        } else {
            // ---------------- xp update (PAN domain, W=256) ----------------
            const int jb  = g * (GRP_BLKS - XC_BLK_PER_GRP) + (j - XC_BLK_PER_GRP);
            const int pix = (jb * 128 + threadIdx.x) * 2;   // even
            const float wA = mup * invp;
            const float wz = mu_ * invp;
            const int b   = pix / HWP;
            const int rem = pix - b * HWP;           // even
            const int h   = rem >> 8;                // WP = 256
            const int w   = rem & 255;               // even
            const int basep = b * (NC * HWP) + rem;              // phi_p/xc_k_1/out
            const int basec = b * (NC * HWC) + h * WCC + w;      // z (shifted), even

            const float2 y2 = *(const float2*)(yp + pix);   // hoisted

            float2 mr[NC], pr[NC];
            float2 s  = make_float2(0.f, 0.f);
            float2 am = make_float2(0.f, 0.f);
            #pragma unroll
            for (int c = 0; c < NC; ++c) {
                // shift_back: z[b,c,h,w+2c], z[b,c,h,w+1+2c]; w+1+2c <= 309, no wrap
                const float2 zv = *(const float2*)(z + basec + c * HWC + 2 * c);
                const int  o  = basep + c * HWP;
                const float2 pv = *(const float2*)(phi_p  + o);
                const float2 xv = *(const float2*)(xc_k_1 + o);
                float2 m;
                m.x = fmaf(wz, xv.x, wA * zv.x);
                m.y = fmaf(wz, xv.y, wA * zv.y);
                mr[c] = m; pr[c] = pv;
                s.x  = fmaf(pv.x, pv.x, s.x);
                s.y  = fmaf(pv.y, pv.y, s.y);
                am.x = fmaf(m.x, pv.x, am.x);
                am.y = fmaf(m.y, pv.y, am.y);
            }
            if (s.x == 0.f) s.x = 1.f;
            if (s.y == 0.f) s.y = 1.f;
            float2 t;
            t.x = __fdividef(y2.x - am.x, mu_ + mup + s.x);
            t.y = __fdividef(y2.y - am.y, mu_ + mup + s.y);

            float* __restrict__ outp = out + XC_ELEMS;
            #pragma unroll
            for (int c = 0; c < NC; ++c) {
                float2 o2;
                o2.x = fmaf(t.x, pr[c].x, mr[c].x);
                o2.y = fmaf(t.y, pr[c].y, mr[c].y);
                *(float2*)(outp + basep + c * HWP) = o2;
            }
        }
    }
}

extern "C" void kernel_launch(void* const* d_in, const int* in_sizes, int n_in,
                              void* d_out, int out_size)
{
    const float* z      = (const float*)d_in[0];
    const float* yc     = (const float*)d_in[1];
    const float* phi_c  = (const float*)d_in[2];
    const float* yp     = (const float*)d_in[3];
    const float* phi_p  = (const float*)d_in[4];
    const float* xc_k_1 = (const float*)d_in[5];
    const float* xp_k_1 = (const float*)d_in[6];
    const float* mu     = (const float*)d_in[7];
    const float* mu_c   = (const float*)d_in[8];
    const float* mu_p   = (const float*)d_in[9];
    float* out = (float*)d_out;

    dp_fused_kernel<<<PERSIST_BLOCKS, 128>>>(z, yc, phi_c, yp, phi_p,
                                             xc_k_1, xp_k_1, mu, mu_c, mu_p, out);
}

// round 14
// speedup vs baseline: 1.0126x; 1.0126x over previous
#include <cuda_runtime.h>

// Problem shapes (compile-time constants)
#define BATCH 8
#define NC    28
#define HH    256
#define WCC   310
#define WPP   256

static constexpr int HWC = HH * WCC;                 // 79360 (even)
static constexpr int HWP = HH * WPP;                 // 65536
static constexpr int NPIX_C = BATCH * HWC;           // 634880
static constexpr int NPIX_P = BATCH * HWP;           // 524288
static constexpr int XC_ELEMS = BATCH * NC * HWC;    // 17,776,640

// FINAL converged configuration (best measured: 70.1us wall, 66.1us kernel,
// 82.7% DRAM / 6551 GB/s — at the compulsory-traffic roofline):
//  - float2: 2 adjacent pixels per thread (float4 spills: R8/R10)
//  - 128-thread blocks, (128,3) bounds -> regs 168, no spill
//  - interleave: 16 groups x (155 xc + 128 xp); each group = half a batch
//    image in both domains so xp's shifted z reads hit L2 (-11% DRAM traffic)
//  - algebraic form: out[c] = m[c] + t*phi[c], m = wA*z + wz*x,
//    t = (y - sum m*phi)/(mu+mu_x+sum phi^2)   [wA+wz=1, A linear]
//  - fast divide in the scalar tail (precision margin: 7e-8 << 1e-3)
//  - rejected by measurement: __ldcs/__stcs (R3/R4), occupancy changes
//    (R5/R6), float4 (R8/R10), persistent CTAs (R13)
static constexpr int XC_BLK_PER_GRP = 155;
static constexpr int GRP_BLKS = 283;

__global__ void __launch_bounds__(128, 3)
dp_fused_kernel(const float* __restrict__ z,
                const float* __restrict__ yc,
                const float* __restrict__ phi_c,
                const float* __restrict__ yp,
                const float* __restrict__ phi_p,
                const float* __restrict__ xc_k_1,
                const float* __restrict__ xp_k_1,
                const float* __restrict__ mu,
                const float* __restrict__ mu_c,
                const float* __restrict__ mu_p,
                float* __restrict__ out)
{
    const int g = blockIdx.x / GRP_BLKS;
    const int j = blockIdx.x - g * GRP_BLKS;
    const float mu_ = mu[0];

    if (j < XC_BLK_PER_GRP) {
        // ---------------- xc update (coded domain, W=310) ----------------
        const int pix = ((g * XC_BLK_PER_GRP + j) * 128 + threadIdx.x) * 2; // even
        const float muc = mu_c[0];
        const float inv = 1.f / (mu_ + muc);
        const float wA  = muc * inv;
        const float wz  = mu_ * inv;
        const int b    = pix / HWC;
        const int rem  = pix - b * HWC;          // even
        const int base = b * (NC * HWC) + rem;   // 8B aligned

        // Hoisted: overlap y's DRAM latency with the channel-load burst.
        const float2 y2 = *(const float2*)(yc + pix);

        float2 mr[NC], pr[NC];
        float2 s  = make_float2(0.f, 0.f);
        float2 am = make_float2(0.f, 0.f);
        #pragma unroll
        for (int c = 0; c < NC; ++c) {
            const int o = base + c * HWC;
            const float2 zv = *(const float2*)(z      + o);
            const float2 pv = *(const float2*)(phi_c  + o);
            const float2 xv = *(const float2*)(xp_k_1 + o);
            float2 m;
            m.x = fmaf(wz, xv.x, wA * zv.x);
            m.y = fmaf(wz, xv.y, wA * zv.y);
            mr[c] = m; pr[c] = pv;
            s.x  = fmaf(pv.x, pv.x, s.x);
            s.y  = fmaf(pv.y, pv.y, s.y);
            am.x = fmaf(m.x, pv.x, am.x);
            am.y = fmaf(m.y, pv.y, am.y);
        }
        if (s.x == 0.f) s.x = 1.f;
        if (s.y == 0.f) s.y = 1.f;
        float2 t;
        t.x = __fdividef(y2.x - am.x, mu_ + muc + s.x);
        t.y = __fdividef(y2.y - am.y, mu_ + muc + s.y);

        #pragma unroll
        for (int c = 0; c < NC; ++c) {
            float2 o2;
            o2.x = fmaf(t.x, pr[c].x, mr[c].x);
            o2.y = fmaf(t.y, pr[c].y, mr[c].y);
            *(float2*)(out + base + c * HWC) = o2;
        }
    } else {
        // ---------------- xp update (PAN domain, W=256) ----------------
        const int jb  = g * (GRP_BLKS - XC_BLK_PER_GRP) + (j - XC_BLK_PER_GRP);
        const int pix = (jb * 128 + threadIdx.x) * 2;   // even
        const float mup = mu_p[0];
        const float inv = 1.f / (mu_ + mup);
        const float wA  = mup * inv;
        const float wz  = mu_ * inv;
        const int b   = pix / HWP;
        const int rem = pix - b * HWP;           // even
        const int h   = rem >> 8;                // WP = 256
        const int w   = rem & 255;               // even
        const int basep = b * (NC * HWP) + rem;                 // phi_p / xc_k_1 / out
        const int basec = b * (NC * HWC) + h * WCC + w;         // z (shifted), even

        const float2 y2 = *(const float2*)(yp + pix);  // hoisted

        float2 mr[NC], pr[NC];
        float2 s  = make_float2(0.f, 0.f);
        float2 am = make_float2(0.f, 0.f);
        #pragma unroll
        for (int c = 0; c < NC; ++c) {
            // shift_back: z[b,c,h,w+2c] and z[b,c,h,w+1+2c]; w+1+2c <= 309, no wrap.
            const float2 zv = *(const float2*)(z + basec + c * HWC + 2 * c);
            const int  o  = basep + c * HWP;
            const float2 pv = *(const float2*)(phi_p  + o);
            const float2 xv = *(const float2*)(xc_k_1 + o);
            float2 m;
            m.x = fmaf(wz, xv.x, wA * zv.x);
            m.y = fmaf(wz, xv.y, wA * zv.y);
            mr[c] = m; pr[c] = pv;
            s.x  = fmaf(pv.x, pv.x, s.x);
            s.y  = fmaf(pv.y, pv.y, s.y);
            am.x = fmaf(m.x, pv.x, am.x);
            am.y = fmaf(m.y, pv.y, am.y);
        }
        if (s.x == 0.f) s.x = 1.f;
        if (s.y == 0.f) s.y = 1.f;
        float2 t;
        t.x = __fdividef(y2.x - am.x, mu_ + mup + s.x);
        t.y = __fdividef(y2.y - am.y, mu_ + mup + s.y);

        float* __restrict__ outp = out + XC_ELEMS;
        #pragma unroll
        for (int c = 0; c < NC; ++c) {
            float2 o2;
            o2.x = fmaf(t.x, pr[c].x, mr[c].x);
            o2.y = fmaf(t.y, pr[c].y, mr[c].y);
            *(float2*)(outp + basep + c * HWP) = o2;
        }
    }
}

extern "C" void kernel_launch(void* const* d_in, const int* in_sizes, int n_in,
                              void* d_out, int out_size)
{
    const float* z      = (const float*)d_in[0];
    const float* yc     = (const float*)d_in[1];
    const float* phi_c  = (const float*)d_in[2];
    const float* yp     = (const float*)d_in[3];
    const float* phi_p  = (const float*)d_in[4];
    const float* xc_k_1 = (const float*)d_in[5];
    const float* xp_k_1 = (const float*)d_in[6];
    const float* mu     = (const float*)d_in[7];
    const float* mu_c   = (const float*)d_in[8];
    const float* mu_p   = (const float*)d_in[9];
    float* out = (float*)d_out;

    const int blocks = (NPIX_C + NPIX_P) / 256;   // 4528 = 16 * 283
    dp_fused_kernel<<<blocks, 128>>>(z, yc, phi_c, yp, phi_p,
                                     xc_k_1, xp_k_1, mu, mu_c, mu_p, out);
}

// round 15
// speedup vs baseline: 1.0265x; 1.0137x over previous
#include <cuda_runtime.h>

// Problem shapes (compile-time constants)
#define BATCH 8
#define NC    28
#define HH    256
#define WCC   310
#define WPP   256

static constexpr int HWC = HH * WCC;                 // 79360 (even)
static constexpr int HWP = HH * WPP;                 // 65536
static constexpr int NPIX_C = BATCH * HWC;           // 634880
static constexpr int NPIX_P = BATCH * HWP;           // 524288
static constexpr int XC_ELEMS = BATCH * NC * HWC;    // 17,776,640

// FINAL converged configuration — at the compulsory-traffic memory roofline.
// Measured (two independent runs of this exact binary): 70.1/71.1us wall,
// 66.1/66.3us kernel, 82.6-82.7% DRAM, 6549-6551 GB/s, rel_err 7.0e-8.
// Floor: ~462 MB compulsory traffic / 6.55 TB/s best-sustained = ~70.5us.
//
//  - float2: 2 adjacent pixels per thread (float4 hits the register wall
//    and spills: R8 @(128,3), R10 @(128,2))
//  - 128-thread blocks, (128,3) bounds -> regs 168, no spill
//  - block-schedule interleave: 16 groups x (155 xc + 128 xp); each group
//    covers half a batch image in both domains so the xp path's shifted z
//    reads hit the z lines the xc blocks just pulled into L2 (-11% traffic)
//  - algebraic form (wA+wz=1, A linear): out[c] = m[c] + t*phi[c],
//    m = wA*z + wz*x,  t = (y - sum m*phi)/(mu + mu_x + sum phi^2)
//  - fast divide in the scalar tail (4 decades of precision margin)
//  - rejected by measurement: __ldcs/__stcs (R3/R4), occupancy 2<->3 CTA
//    (R5/R6), float4 (R8/R10), persistent CTAs (R13)
static constexpr int XC_BLK_PER_GRP = 155;
static constexpr int GRP_BLKS = 283;

__global__ void __launch_bounds__(128, 3)
dp_fused_kernel(const float* __restrict__ z,
                const float* __restrict__ yc,
                const float* __restrict__ phi_c,
                const float* __restrict__ yp,
                const float* __restrict__ phi_p,
                const float* __restrict__ xc_k_1,
                const float* __restrict__ xp_k_1,
                const float* __restrict__ mu,
                const float* __restrict__ mu_c,
                const float* __restrict__ mu_p,
                float* __restrict__ out)
{
    const int g = blockIdx.x / GRP_BLKS;
    const int j = blockIdx.x - g * GRP_BLKS;
    const float mu_ = mu[0];

    if (j < XC_BLK_PER_GRP) {
        // ---------------- xc update (coded domain, W=310) ----------------
        const int pix = ((g * XC_BLK_PER_GRP + j) * 128 + threadIdx.x) * 2; // even
        const float muc = mu_c[0];
        const float inv = 1.f / (mu_ + muc);
        const float wA  = muc * inv;
        const float wz  = mu_ * inv;
        const int b    = pix / HWC;
        const int rem  = pix - b * HWC;          // even
        const int base = b * (NC * HWC) + rem;   // 8B aligned

        // Hoisted: overlap y's DRAM latency with the channel-load burst.
        const float2 y2 = *(const float2*)(yc + pix);

        float2 mr[NC], pr[NC];
        float2 s  = make_float2(0.f, 0.f);
        float2 am = make_float2(0.f, 0.f);
        #pragma unroll
        for (int c = 0; c < NC; ++c) {
            const int o = base + c * HWC;
            const float2 zv = *(const float2*)(z      + o);
            const float2 pv = *(const float2*)(phi_c  + o);
            const float2 xv = *(const float2*)(xp_k_1 + o);
            float2 m;
            m.x = fmaf(wz, xv.x, wA * zv.x);
            m.y = fmaf(wz, xv.y, wA * zv.y);
            mr[c] = m; pr[c] = pv;
            s.x  = fmaf(pv.x, pv.x, s.x);
            s.y  = fmaf(pv.y, pv.y, s.y);
            am.x = fmaf(m.x, pv.x, am.x);
            am.y = fmaf(m.y, pv.y, am.y);
        }
        if (s.x == 0.f) s.x = 1.f;
        if (s.y == 0.f) s.y = 1.f;
        float2 t;
        t.x = __fdividef(y2.x - am.x, mu_ + muc + s.x);
        t.y = __fdividef(y2.y - am.y, mu_ + muc + s.y);

        #pragma unroll
        for (int c = 0; c < NC; ++c) {
            float2 o2;
            o2.x = fmaf(t.x, pr[c].x, mr[c].x);
            o2.y = fmaf(t.y, pr[c].y, mr[c].y);
            *(float2*)(out + base + c * HWC) = o2;
        }
    } else {
        // ---------------- xp update (PAN domain, W=256) ----------------
        const int jb  = g * (GRP_BLKS - XC_BLK_PER_GRP) + (j - XC_BLK_PER_GRP);
        const int pix = (jb * 128 + threadIdx.x) * 2;   // even
        const float mup = mu_p[0];
        const float inv = 1.f / (mu_ + mup);
        const float wA  = mup * inv;
        const float wz  = mu_ * inv;
        const int b   = pix / HWP;
        const int rem = pix - b * HWP;           // even
        const int h   = rem >> 8;                // WP = 256
        const int w   = rem & 255;               // even
        const int basep = b * (NC * HWP) + rem;                 // phi_p / xc_k_1 / out
        const int basec = b * (NC * HWC) + h * WCC + w;         // z (shifted), even

        const float2 y2 = *(const float2*)(yp + pix);  // hoisted

        float2 mr[NC], pr[NC];
        float2 s  = make_float2(0.f, 0.f);
        float2 am = make_float2(0.f, 0.f);
        #pragma unroll
        for (int c = 0; c < NC; ++c) {
            // shift_back: z[b,c,h,w+2c] and z[b,c,h,w+1+2c]; w+1+2c <= 309, no wrap.
            const float2 zv = *(const float2*)(z + basec + c * HWC + 2 * c);
            const int  o  = basep + c * HWP;
            const float2 pv = *(const float2*)(phi_p  + o);
            const float2 xv = *(const float2*)(xc_k_1 + o);
            float2 m;
            m.x = fmaf(wz, xv.x, wA * zv.x);
            m.y = fmaf(wz, xv.y, wA * zv.y);
            mr[c] = m; pr[c] = pv;
            s.x  = fmaf(pv.x, pv.x, s.x);
            s.y  = fmaf(pv.y, pv.y, s.y);
            am.x = fmaf(m.x, pv.x, am.x);
            am.y = fmaf(m.y, pv.y, am.y);
        }
        if (s.x == 0.f) s.x = 1.f;
        if (s.y == 0.f) s.y = 1.f;
        float2 t;
        t.x = __fdividef(y2.x - am.x, mu_ + mup + s.x);
        t.y = __fdividef(y2.y - am.y, mu_ + mup + s.y);

        float* __restrict__ outp = out + XC_ELEMS;
        #pragma unroll
        for (int c = 0; c < NC; ++c) {
            float2 o2;
            o2.x = fmaf(t.x, pr[c].x, mr[c].x);
            o2.y = fmaf(t.y, pr[c].y, mr[c].y);
            *(float2*)(outp + basep + c * HWP) = o2;
        }
    }
}

extern "C" void kernel_launch(void* const* d_in, const int* in_sizes, int n_in,
                              void* d_out, int out_size)
{
    const float* z      = (const float*)d_in[0];
    const float* yc     = (const float*)d_in[1];
    const float* phi_c  = (const float*)d_in[2];
    const float* yp     = (const float*)d_in[3];
    const float* phi_p  = (const float*)d_in[4];
    const float* xc_k_1 = (const float*)d_in[5];
    const float* xp_k_1 = (const float*)d_in[6];
    const float* mu     = (const float*)d_in[7];
    const float* mu_c   = (const float*)d_in[8];
    const float* mu_p   = (const float*)d_in[9];
    float* out = (float*)d_out;

    const int blocks = (NPIX_C + NPIX_P) / 256;   // 4528 = 16 * 283
    dp_fused_kernel<<<blocks, 128>>>(z, yc, phi_c, yp, phi_p,
                                     xc_k_1, xp_k_1, mu, mu_c, mu_p, out);
}